// round 4
// baseline (speedup 1.0000x reference)
#include <cuda_runtime.h>
#include <cuda_fp16.h>
#include <cstdint>

// Shapes fixed by reference: outputs [8192,64] f32, labels [8192] i32
#define BQ 8192
#define DD 64
#define TM 128
#define TN 128
#define NB (BQ / TM)                 // 64 tile-rows
#define NTILES (NB * (NB + 1) / 2)   // 2080 upper-triangle tiles (incl. diagonal)

// Scratch (__device__ globals: allocation-free rule)
__device__ __half g_Ah[BQ * DD];
__device__ float  g_sq[BQ];
__device__ float  g_partial[NTILES];

// ---------------------------------------------------------------------------
// Kernel 1: f32 -> f16 + row squared norms (of the rounded values)
// ---------------------------------------------------------------------------
__global__ __launch_bounds__(256) void prep_kernel(const float* __restrict__ outputs) {
    const int row  = blockIdx.x * 8 + (threadIdx.x >> 5);
    const int lane = threadIdx.x & 31;
    float2 v = ((const float2*)(outputs + (size_t)row * DD))[lane];
    __half2 h = __floats2half2_rn(v.x, v.y);
    float f0 = __half2float(__low2half(h));
    float f1 = __half2float(__high2half(h));
    float s = fmaf(f0, f0, f1 * f1);
#pragma unroll
    for (int off = 16; off; off >>= 1)
        s += __shfl_xor_sync(0xFFFFFFFFu, s, off);
    ((__half2*)(g_Ah + (size_t)row * DD))[lane] = h;
    if (lane == 0) g_sq[row] = s;
}

// ---------------------------------------------------------------------------
// helpers
// ---------------------------------------------------------------------------
__device__ __forceinline__ uint32_t smem_u32(const void* p) {
    return (uint32_t)__cvta_generic_to_shared(p);
}
__device__ __forceinline__ void ldmatrix_x4(uint32_t& r0, uint32_t& r1, uint32_t& r2, uint32_t& r3,
                                            uint32_t addr) {
    asm volatile("ldmatrix.sync.aligned.m8n8.x4.shared.b16 {%0,%1,%2,%3}, [%4];"
                 : "=r"(r0), "=r"(r1), "=r"(r2), "=r"(r3) : "r"(addr));
}
// f16-accumulate mma: D,C are 2 regs (half2 x2)
__device__ __forceinline__ void mma16816_f16(uint32_t* c, const uint32_t* a, const uint32_t* b) {
    asm volatile(
        "mma.sync.aligned.m16n8k16.row.col.f16.f16.f16.f16 "
        "{%0,%1}, {%2,%3,%4,%5}, {%6,%7}, {%0,%1};"
        : "+r"(c[0]), "+r"(c[1])
        : "r"(a[0]), "r"(a[1]), "r"(a[2]), "r"(a[3]), "r"(b[0]), "r"(b[1]));
}
__device__ __forceinline__ float qroot_mufu(float d2) {   // d2^(1/4), MUFU pipe
    float s1, s2;
    asm("sqrt.approx.f32 %0, %1;" : "=f"(s1) : "f"(d2));
    asm("sqrt.approx.f32 %0, %1;" : "=f"(s2) : "f"(s1));
    return s2;
}
__device__ __forceinline__ float qroot_fma(float x) {     // d2^(1/4), FMA pipe only
    uint32_t i = __float_as_uint(x);
    float r = __uint_as_float(0x4F5C8FE4u - (i >> 2));    // r ~ x^(-1/4), ~1.3% err
    float r2 = r * r, r4 = r2 * r2, t = x * r4;
    r = r * fmaf(t, -0.25f, 1.25f);                       // Newton 1
    r2 = r * r; r4 = r2 * r2; t = x * r4;
    r = r * fmaf(t, -0.25f, 1.25f);                       // Newton 2 (~1e-7 rel)
    return (x * r) * (r * r);                             // x^(1/4)
}

// ---------------------------------------------------------------------------
// Kernel 2: one CTA per upper-triangle 128x128 tile, 8 warps, warp-tile 32x64.
// f16-accumulate HMMA Gram (regs), fused epilogue w/ MUFU+FMA qroot split.
// ---------------------------------------------------------------------------
#define PAD 72  // halves per smem row (144B rows, 16B aligned, conflict-free ldmatrix)

__global__ __launch_bounds__(256, 3) void pair_kernel(const int* __restrict__ labels) {
    __shared__ __half sA[TM][PAD];
    __shared__ __half sB[TN][PAD];
    __shared__ float  sqA[TM], sqB[TN];
    __shared__ int    labA[TM], labB[TN];
    __shared__ float  wsum[8];

    const int t   = blockIdx.x;
    const int tid = threadIdx.x;

    // Decode linear tile id -> (bi, bj), bi <= bj, row-major upper triangle
    int bi = (int)((double)NB + 0.5 -
                   sqrt(((double)NB + 0.5) * ((double)NB + 0.5) - 2.0 * (double)t));
    if (bi < 0) bi = 0;
    if (bi > NB - 1) bi = NB - 1;
    while (bi > 0 && (bi * NB - bi * (bi - 1) / 2) > t) bi--;
    while (((bi + 1) * NB - (bi + 1) * bi / 2) <= t) bi++;
    const int bj = bi + (t - (bi * NB - bi * (bi - 1) / 2));
    const bool diag = (bi == bj);
    const int rowA0 = bi * TM;
    const int rowB0 = bj * TN;

    // Fill tiles: 128 rows x 8 int4-chunks each
    for (int v = tid; v < TM * 8; v += 256) {
        int r = v >> 3;
        int c = (v & 7) * 8;
        *(int4*)&sA[r][c] = *(const int4*)&g_Ah[(size_t)(rowA0 + r) * DD + c];
        *(int4*)&sB[r][c] = *(const int4*)&g_Ah[(size_t)(rowB0 + r) * DD + c];
    }
    if (tid < TM) {
        sqA[tid]  = g_sq[rowA0 + tid];
        sqB[tid]  = g_sq[rowB0 + tid];
        labA[tid] = labels[rowA0 + tid];
        labB[tid] = labels[rowB0 + tid];
    }
    __syncthreads();

    // Warp tiling: 4 warps along M (32 rows), 2 along N (64 cols)
    const int w    = tid >> 5;
    const int lane = tid & 31;
    const int wrow = (w & 3) * 32;
    const int wcol = (w >> 2) * 64;
    const int g    = lane >> 2;   // row within 8-group
    const int t4   = lane & 3;    // col pair index

    uint32_t acc[2][8][2];        // f16x2 accumulators: [mi][ni][h]
#pragma unroll
    for (int mi = 0; mi < 2; mi++)
#pragma unroll
        for (int ni = 0; ni < 8; ni++) {
            acc[mi][ni][0] = 0u; acc[mi][ni][1] = 0u;
        }

    const int lq = lane >> 3;     // 0..3
    const int lr = lane & 7;

#pragma unroll
    for (int k = 0; k < 4; k++) {
        const int kb = k * 16;
        uint32_t af[2][4];
#pragma unroll
        for (int mi = 0; mi < 2; mi++) {
            int m0 = wrow + 16 * mi;
            int arow = m0 + lr + ((lq & 1) ? 8 : 0);
            int acol = kb + ((lq & 2) ? 8 : 0);
            ldmatrix_x4(af[mi][0], af[mi][1], af[mi][2], af[mi][3],
                        smem_u32(&sA[arow][acol]));
        }
        // B: one x4 covers two ni (matrices: (n0,k0),(n0+8,k0),(n0,k0+8),(n0+8,k0+8))
#pragma unroll
        for (int ni2 = 0; ni2 < 4; ni2++) {
            int n0 = wcol + 16 * ni2;
            int brow = n0 + lr + ((lq & 1) ? 8 : 0);
            int bcol = kb + ((lq & 2) ? 8 : 0);
            uint32_t b0, b1, b2, b3;
            ldmatrix_x4(b0, b1, b2, b3, smem_u32(&sB[brow][bcol]));
            uint32_t bfA[2] = {b0, b2};   // ni = 2*ni2
            uint32_t bfB[2] = {b1, b3};   // ni = 2*ni2+1
#pragma unroll
            for (int mi = 0; mi < 2; mi++) {
                mma16816_f16(acc[mi][2 * ni2 + 0], af[mi], bfA);
                mma16816_f16(acc[mi][2 * ni2 + 1], af[mi], bfB);
            }
        }
    }

    // Epilogue. acc[mi][ni][h] halves -> (row = wrow+16mi+8h+g, col = wcol+8ni+2t4+{0,1})
    float sr_[2][2]; int lr_[2][2]; int rl_[2][2];
#pragma unroll
    for (int mi = 0; mi < 2; mi++)
#pragma unroll
        for (int h = 0; h < 2; h++) {
            int r = wrow + 16 * mi + 8 * h + g;
            rl_[mi][h] = r;
            sr_[mi][h] = sqA[r];
            lr_[mi][h] = labA[r];
        }

    float accsum = 0.f;
#pragma unroll
    for (int ni = 0; ni < 8; ni++) {
        const int c0 = wcol + 8 * ni + 2 * t4;
        const float sc0 = sqB[c0], sc1 = sqB[c0 + 1];
        const int   lc0 = labB[c0], lc1 = labB[c0 + 1];
        const bool useFma = (ni == 0) || (ni == 4);   // 25% of elems on FMA pipe
#pragma unroll
        for (int mi = 0; mi < 2; mi++)
#pragma unroll
            for (int h = 0; h < 2; h++) {
                float2 gpair = __half22float2(*(const __half2*)&acc[mi][ni][h]);
                float sr = sr_[mi][h];
                int   lrow = lr_[mi][h];
                float d2a = fmaf(-2.f, gpair.x, sr + sc0);
                float d2b = fmaf(-2.f, gpair.y, sr + sc1);
                float da, db;
                if (diag) {
                    da = qroot_mufu(fmaxf(d2a, 0.f));
                    db = qroot_mufu(fmaxf(d2b, 0.f));
                } else if (useFma) {
                    da = qroot_fma(d2a);
                    db = qroot_fma(d2b);
                } else {
                    da = qroot_mufu(d2a);
                    db = qroot_mufu(d2b);
                }
                float wa = (lrow == lc0) ? 5.f : -1.f;
                float wb = (lrow == lc1) ? 5.f : -1.f;
                if (diag) {
                    if (c0 <= rl_[mi][h])     wa = 0.f;
                    if (c0 + 1 <= rl_[mi][h]) wb = 0.f;
                }
                accsum = fmaf(da, wa, accsum);
                accsum = fmaf(db, wb, accsum);
            }
    }

    // Deterministic block reduce -> per-CTA partial
#pragma unroll
    for (int off = 16; off; off >>= 1)
        accsum += __shfl_xor_sync(0xFFFFFFFFu, accsum, off);
    if (lane == 0) wsum[w] = accsum;
    __syncthreads();
    if (tid == 0) {
        float s = 0.f;
#pragma unroll
        for (int i = 0; i < 8; i++) s += wsum[i];
        g_partial[blockIdx.x] = s;
    }
}

// ---------------------------------------------------------------------------
// Kernel 3: deterministic final reduction
// ---------------------------------------------------------------------------
__global__ void reduce_kernel(float* __restrict__ out) {
    __shared__ float sh[256];
    float s = 0.f;
    for (int i = threadIdx.x; i < NTILES; i += 256)
        s += g_partial[i];
    sh[threadIdx.x] = s;
    __syncthreads();
    for (int off = 128; off; off >>= 1) {
        if (threadIdx.x < off) sh[threadIdx.x] += sh[threadIdx.x + off];
        __syncthreads();
    }
    if (threadIdx.x == 0) out[0] = sh[0];
}

extern "C" void kernel_launch(void* const* d_in, const int* in_sizes, int n_in,
                              void* d_out, int out_size) {
    const float* outputs = (const float*)d_in[0];
    const int*   labels  = (const int*)d_in[1];
    float*       out     = (float*)d_out;

    prep_kernel<<<BQ / 8, 256>>>(outputs);
    pair_kernel<<<NTILES, 256>>>(labels);
    reduce_kernel<<<1, 256>>>(out);
}

// round 5
// speedup vs baseline: 1.0721x; 1.0721x over previous
#include <cuda_runtime.h>
#include <cuda_fp16.h>
#include <cstdint>

// Shapes fixed by reference: outputs [8192,64] f32, labels [8192] i32
#define BQ 8192
#define DD 64
#define TM 128
#define TN 128
#define NB (BQ / TM)                 // 64 tile-rows
#define NTILES (NB * (NB + 1) / 2)   // 2080 upper-triangle tiles (incl. diagonal)

// Scratch (__device__ globals: allocation-free rule)
__device__ __half g_Ah[BQ * DD];
__device__ float  g_sq[BQ];
__device__ float  g_partial[NTILES];

// ---------------------------------------------------------------------------
// Kernel 1: f32 -> f16 + row squared norms. Quarter-warp (16 lanes) per row,
// float4 per lane.
// ---------------------------------------------------------------------------
__global__ __launch_bounds__(256) void prep_kernel(const float* __restrict__ outputs) {
    const int warp = blockIdx.x * 8 + (threadIdx.x >> 5);
    const int lane = threadIdx.x & 31;
    const int row  = warp * 2 + (lane >> 4);
    const int idx  = lane & 15;
    float4 v = ((const float4*)(outputs + (size_t)row * DD))[idx];
    __half2 h01 = __floats2half2_rn(v.x, v.y);
    __half2 h23 = __floats2half2_rn(v.z, v.w);
    float2 f01 = __half22float2(h01);
    float2 f23 = __half22float2(h23);
    float s = fmaf(f01.x, f01.x, f01.y * f01.y) + fmaf(f23.x, f23.x, f23.y * f23.y);
#pragma unroll
    for (int off = 8; off; off >>= 1)
        s += __shfl_xor_sync(0xFFFFFFFFu, s, off);
    uint2 pk;
    pk.x = *(const uint32_t*)&h01;
    pk.y = *(const uint32_t*)&h23;
    ((uint2*)(g_Ah + (size_t)row * DD))[idx] = pk;
    if (idx == 0) g_sq[row] = s;
}

// ---------------------------------------------------------------------------
// helpers
// ---------------------------------------------------------------------------
__device__ __forceinline__ uint32_t smem_u32(const void* p) {
    return (uint32_t)__cvta_generic_to_shared(p);
}
__device__ __forceinline__ void ldmatrix_x4(uint32_t& r0, uint32_t& r1, uint32_t& r2, uint32_t& r3,
                                            uint32_t addr) {
    asm volatile("ldmatrix.sync.aligned.m8n8.x4.shared.b16 {%0,%1,%2,%3}, [%4];"
                 : "=r"(r0), "=r"(r1), "=r"(r2), "=r"(r3) : "r"(addr));
}
__device__ __forceinline__ void mma16816_f16(uint32_t* c, const uint32_t* a,
                                             uint32_t b0, uint32_t b1) {
    asm volatile(
        "mma.sync.aligned.m16n8k16.row.col.f16.f16.f16.f16 "
        "{%0,%1}, {%2,%3,%4,%5}, {%6,%7}, {%0,%1};"
        : "+r"(c[0]), "+r"(c[1])
        : "r"(a[0]), "r"(a[1]), "r"(a[2]), "r"(a[3]), "r"(b0), "r"(b1));
}
__device__ __forceinline__ float qroot_mufu(float d2) {   // d2^(1/4), MUFU pipe
    float s1, s2;
    asm("sqrt.approx.f32 %0, %1;" : "=f"(s1) : "f"(d2));
    asm("sqrt.approx.f32 %0, %1;" : "=f"(s2) : "f"(s1));
    return s2;
}
__device__ __forceinline__ float qroot_fma(float x) {     // d2^(1/4), FMA pipe only
    uint32_t i = __float_as_uint(x);
    float r = __uint_as_float(0x4F5C8FE4u - (i >> 2));    // r ~ x^(-1/4)
    float r2 = r * r, r4 = r2 * r2, t = x * r4;
    r = r * fmaf(t, -0.25f, 1.25f);                       // Newton 1
    r2 = r * r; r4 = r2 * r2; t = x * r4;
    r = r * fmaf(t, -0.25f, 1.25f);                       // Newton 2
    return (x * r) * (r * r);                             // x^(1/4)
}

// ---------------------------------------------------------------------------
// Kernel 2: one CTA per upper-triangle 128x128 tile, 8 warps, warp-tile 32x64.
// A-fragments resident; per-ni2 MMA + immediate half2 epilogue.
// ---------------------------------------------------------------------------
#define PAD 72  // halves per smem row (144B rows: conflict-free ldmatrix)

__global__ __launch_bounds__(256, 3) void pair_kernel(const int* __restrict__ labels) {
    __shared__ __half sA[TM][PAD];
    __shared__ __half sB[TN][PAD];
    __shared__ __half sqAh[TM], sqBh[TN];
    __shared__ int    labA[TM], labB[TN];
    __shared__ float  wsum[8];

    const int t   = blockIdx.x;
    const int tid = threadIdx.x;

    // Decode linear tile id -> (bi, bj), bi <= bj, row-major upper triangle
    int bi = (int)((double)NB + 0.5 -
                   sqrt(((double)NB + 0.5) * ((double)NB + 0.5) - 2.0 * (double)t));
    if (bi < 0) bi = 0;
    if (bi > NB - 1) bi = NB - 1;
    while (bi > 0 && (bi * NB - bi * (bi - 1) / 2) > t) bi--;
    while (((bi + 1) * NB - (bi + 1) * bi / 2) <= t) bi++;
    const int bj = bi + (t - (bi * NB - bi * (bi - 1) / 2));
    const bool diag = (bi == bj);
    const int rowA0 = bi * TM;
    const int rowB0 = bj * TN;

    // Fill tiles
    for (int v = tid; v < TM * 8; v += 256) {
        int r = v >> 3;
        int c = (v & 7) * 8;
        *(int4*)&sA[r][c] = *(const int4*)&g_Ah[(size_t)(rowA0 + r) * DD + c];
        *(int4*)&sB[r][c] = *(const int4*)&g_Ah[(size_t)(rowB0 + r) * DD + c];
    }
    if (tid < TM) {
        sqAh[tid] = __float2half_rn(g_sq[rowA0 + tid]);
        sqBh[tid] = __float2half_rn(g_sq[rowB0 + tid]);
        labA[tid] = labels[rowA0 + tid];
        labB[tid] = labels[rowB0 + tid];
    }
    __syncthreads();

    const int w    = tid >> 5;
    const int lane = tid & 31;
    const int wrow = (w & 3) * 32;
    const int wcol = (w >> 2) * 64;
    const int g    = lane >> 2;
    const int t4   = lane & 3;
    const int lq   = lane >> 3;
    const int lr   = lane & 7;

    // A fragments: all 4 k-blocks resident (32 regs)
    uint32_t af[2][4][4];
#pragma unroll
    for (int mi = 0; mi < 2; mi++) {
        const int arow = wrow + 16 * mi + lr + ((lq & 1) ? 8 : 0);
#pragma unroll
        for (int k = 0; k < 4; k++) {
            const int acol = k * 16 + ((lq & 2) ? 8 : 0);
            ldmatrix_x4(af[mi][k][0], af[mi][k][1], af[mi][k][2], af[mi][k][3],
                        smem_u32(&sA[arow][acol]));
        }
    }

    // Per-row constants
    __half2 srh2[2][2];
    int     labR[2][2];
#pragma unroll
    for (int mi = 0; mi < 2; mi++)
#pragma unroll
        for (int h = 0; h < 2; h++) {
            int r = wrow + 16 * mi + 8 * h + g;
            srh2[mi][h] = __half2half2(sqAh[r]);
            labR[mi][h] = labA[r];
        }

    const __half2 neg2 = __float2half2_rn(-2.f);
    float acc_all = 0.f, acc_same = 0.f;

#pragma unroll
    for (int ni2 = 0; ni2 < 4; ni2++) {
        // MMA for this ni pair (cols wcol+16*ni2 .. +15)
        uint32_t ac[2][2][2];
#pragma unroll
        for (int mi = 0; mi < 2; mi++)
#pragma unroll
            for (int ns = 0; ns < 2; ns++) { ac[mi][ns][0] = 0u; ac[mi][ns][1] = 0u; }

        const int brow = wcol + 16 * ni2 + lr + ((lq & 1) ? 8 : 0);
#pragma unroll
        for (int k = 0; k < 4; k++) {
            uint32_t b0, b1, b2, b3;
            ldmatrix_x4(b0, b1, b2, b3,
                        smem_u32(&sB[brow][k * 16 + ((lq & 2) ? 8 : 0)]));
#pragma unroll
            for (int mi = 0; mi < 2; mi++) {
                mma16816_f16(ac[mi][0], af[mi][k], b0, b2);   // ni = 2*ni2
                mma16816_f16(ac[mi][1], af[mi][k], b1, b3);   // ni = 2*ni2+1
            }
        }

        // Epilogue for the 2 ni of this pair
        const bool useF = (ni2 == 0) && !diag;   // 25% of elems on FMA pipe
#pragma unroll
        for (int ns = 0; ns < 2; ns++) {
            const int ni = 2 * ni2 + ns;
            const int c0 = wcol + 8 * ni + 2 * t4;
            const __half2 sc = *(const __half2*)&sqBh[c0];
            const int2 lc = *(const int2*)&labB[c0];
#pragma unroll
            for (int mi = 0; mi < 2; mi++)
#pragma unroll
                for (int h = 0; h < 2; h++) {
                    __half2 g2  = *(const __half2*)&ac[mi][ns][h];
                    __half2 d2h = __hfma2(g2, neg2, __hadd2(srh2[mi][h], sc));
                    float d2a = __low2float(d2h);
                    float d2b = __high2float(d2h);
                    float da, db;
                    if (useF) {
                        da = qroot_fma(fmaxf(d2a, 0.f));
                        db = qroot_fma(fmaxf(d2b, 0.f));
                    } else {
                        da = qroot_mufu(fmaxf(d2a, 0.f));
                        db = qroot_mufu(fmaxf(d2b, 0.f));
                    }
                    if (diag) {
                        const int rv = wrow + 16 * mi + 8 * h + g;
                        if (c0 > rv) {
                            acc_all += da;
                            if (labR[mi][h] == lc.x) acc_same += da;
                        }
                        if (c0 + 1 > rv) {
                            acc_all += db;
                            if (labR[mi][h] == lc.y) acc_same += db;
                        }
                    } else {
                        acc_all += da;
                        if (labR[mi][h] == lc.x) acc_same += da;
                        acc_all += db;
                        if (labR[mi][h] == lc.y) acc_same += db;
                    }
                }
        }
    }

    // sum = 6 * sum_same - sum_all  (same-label: 5, diff-label: -1)
    float accsum = fmaf(6.f, acc_same, -acc_all);

    // Deterministic block reduce -> per-CTA partial
#pragma unroll
    for (int off = 16; off; off >>= 1)
        accsum += __shfl_xor_sync(0xFFFFFFFFu, accsum, off);
    if (lane == 0) wsum[w] = accsum;
    __syncthreads();
    if (tid == 0) {
        float s = 0.f;
#pragma unroll
        for (int i = 0; i < 8; i++) s += wsum[i];
        g_partial[blockIdx.x] = s;
    }
}

// ---------------------------------------------------------------------------
// Kernel 3: deterministic final reduction
// ---------------------------------------------------------------------------
__global__ void reduce_kernel(float* __restrict__ out) {
    __shared__ float sh[512];
    float s = 0.f;
    for (int i = threadIdx.x; i < NTILES; i += 512)
        s += g_partial[i];
    sh[threadIdx.x] = s;
    __syncthreads();
    for (int off = 256; off; off >>= 1) {
        if (threadIdx.x < off) sh[threadIdx.x] += sh[threadIdx.x + off];
        __syncthreads();
    }
    if (threadIdx.x == 0) out[0] = sh[0];
}

extern "C" void kernel_launch(void* const* d_in, const int* in_sizes, int n_in,
                              void* d_out, int out_size) {
    const float* outputs = (const float*)d_in[0];
    const int*   labels  = (const int*)d_in[1];
    float*       out     = (float*)d_out;

    prep_kernel<<<BQ / 16, 256>>>(outputs);
    pair_kernel<<<NTILES, 256>>>(labels);
    reduce_kernel<<<1, 512>>>(out);
}

// round 6
// speedup vs baseline: 1.1800x; 1.1007x over previous
#include <cuda_runtime.h>
#include <cuda_fp16.h>
#include <cstdint>

// Shapes fixed by reference: outputs [8192,64] f32, labels [8192] i32
#define BQ 8192
#define DD 64
#define TM 128
#define TN 128
#define NB (BQ / TM)                 // 64 tile-rows
#define NTILES (NB * (NB + 1) / 2)   // 2080 upper-triangle tiles (incl. diagonal)

__device__ __half g_Ah[BQ * DD];
__device__ float  g_sq[BQ];
__device__ float  g_partial[NTILES];

// ---------------------------------------------------------------------------
// Kernel 1: f32 -> f16 + row squared norms. 16 lanes per row, float4 per lane.
// ---------------------------------------------------------------------------
__global__ __launch_bounds__(256) void prep_kernel(const float* __restrict__ outputs) {
    const int warp = blockIdx.x * 8 + (threadIdx.x >> 5);
    const int lane = threadIdx.x & 31;
    const int row  = warp * 2 + (lane >> 4);
    const int idx  = lane & 15;
    float4 v = ((const float4*)(outputs + (size_t)row * DD))[idx];
    __half2 h01 = __floats2half2_rn(v.x, v.y);
    __half2 h23 = __floats2half2_rn(v.z, v.w);
    float2 f01 = __half22float2(h01);
    float2 f23 = __half22float2(h23);
    float s = fmaf(f01.x, f01.x, f01.y * f01.y) + fmaf(f23.x, f23.x, f23.y * f23.y);
#pragma unroll
    for (int off = 8; off; off >>= 1)
        s += __shfl_xor_sync(0xFFFFFFFFu, s, off);
    uint2 pk;
    pk.x = *(const uint32_t*)&h01;
    pk.y = *(const uint32_t*)&h23;
    ((uint2*)(g_Ah + (size_t)row * DD))[idx] = pk;
    if (idx == 0) g_sq[row] = s;
}

// ---------------------------------------------------------------------------
// helpers
// ---------------------------------------------------------------------------
__device__ __forceinline__ uint32_t smem_u32(const void* p) {
    return (uint32_t)__cvta_generic_to_shared(p);
}
__device__ __forceinline__ void ldmatrix_x4(uint32_t& r0, uint32_t& r1, uint32_t& r2, uint32_t& r3,
                                            uint32_t addr) {
    asm volatile("ldmatrix.sync.aligned.m8n8.x4.shared.b16 {%0,%1,%2,%3}, [%4];"
                 : "=r"(r0), "=r"(r1), "=r"(r2), "=r"(r3) : "r"(addr));
}
// NON-volatile: pure register op -> ptxas may schedule/interleave freely
__device__ __forceinline__ void mma16816_f16(uint32_t* c, const uint32_t* a,
                                             uint32_t b0, uint32_t b1) {
    asm("mma.sync.aligned.m16n8k16.row.col.f16.f16.f16.f16 "
        "{%0,%1}, {%2,%3,%4,%5}, {%6,%7}, {%0,%1};"
        : "+r"(c[0]), "+r"(c[1])
        : "r"(a[0]), "r"(a[1]), "r"(a[2]), "r"(a[3]), "r"(b0), "r"(b1));
}
__device__ __forceinline__ float qroot_mufu(float d2) {   // d2^(1/4) (non-volatile)
    float s1, s2;
    asm("sqrt.approx.f32 %0, %1;" : "=f"(s1) : "f"(d2));
    asm("sqrt.approx.f32 %0, %1;" : "=f"(s2) : "f"(s1));
    return s2;
}
__device__ __forceinline__ float qroot_fma(float x) {     // d2^(1/4), FMA pipe only
    uint32_t i = __float_as_uint(x);
    float r = __uint_as_float(0x4F5C8FE4u - (i >> 2));
    float r2 = r * r, r4 = r2 * r2, t = x * r4;
    r = r * fmaf(t, -0.25f, 1.25f);
    r2 = r * r; r4 = r2 * r2; t = x * r4;
    r = r * fmaf(t, -0.25f, 1.25f);
    return (x * r) * (r * r);
}

// ---------------------------------------------------------------------------
// Kernel 2: one CTA per upper-triangle 128x128 tile, 8 warps, warp-tile 32x64.
// ---------------------------------------------------------------------------
#define PAD 72

__global__ __launch_bounds__(256, 3) void pair_kernel(const int* __restrict__ labels) {
    __shared__ __half sA[TM][PAD];
    __shared__ __half sB[TN][PAD];
    __shared__ __half sqAh[TM], sqBh[TN];
    __shared__ __half labAh[TM], labBh[TN];
    __shared__ float  wsum[8];

    const int t   = blockIdx.x;
    const int tid = threadIdx.x;

    // Decode linear tile id -> (bi, bj), bi <= bj
    int bi = (int)((double)NB + 0.5 -
                   sqrt(((double)NB + 0.5) * ((double)NB + 0.5) - 2.0 * (double)t));
    if (bi < 0) bi = 0;
    if (bi > NB - 1) bi = NB - 1;
    while (bi > 0 && (bi * NB - bi * (bi - 1) / 2) > t) bi--;
    while (((bi + 1) * NB - (bi + 1) * bi / 2) <= t) bi++;
    const int bj = bi + (t - (bi * NB - bi * (bi - 1) / 2));
    const bool diag = (bi == bj);
    const int rowA0 = bi * TM;
    const int rowB0 = bj * TN;

    for (int v = tid; v < TM * 8; v += 256) {
        int r = v >> 3;
        int c = (v & 7) * 8;
        *(int4*)&sA[r][c] = *(const int4*)&g_Ah[(size_t)(rowA0 + r) * DD + c];
        *(int4*)&sB[r][c] = *(const int4*)&g_Ah[(size_t)(rowB0 + r) * DD + c];
    }
    if (tid < TM) {
        sqAh[tid]  = __float2half_rn(g_sq[rowA0 + tid]);
        sqBh[tid]  = __float2half_rn(g_sq[rowB0 + tid]);
        labAh[tid] = __int2half_rn(labels[rowA0 + tid]);   // labels 0..9: exact
        labBh[tid] = __int2half_rn(labels[rowB0 + tid]);
    }
    __syncthreads();

    const int w    = tid >> 5;
    const int lane = tid & 31;
    const int wrow = (w & 3) * 32;
    const int wcol = (w >> 2) * 64;
    const int g    = lane >> 2;
    const int t4   = lane & 3;
    const int lq   = lane >> 3;
    const int lr   = lane & 7;

    // A fragments resident (32 regs)
    uint32_t af[2][4][4];
#pragma unroll
    for (int mi = 0; mi < 2; mi++) {
        const int arow = wrow + 16 * mi + lr + ((lq & 1) ? 8 : 0);
#pragma unroll
        for (int k = 0; k < 4; k++) {
            const int acol = k * 16 + ((lq & 2) ? 8 : 0);
            ldmatrix_x4(af[mi][k][0], af[mi][k][1], af[mi][k][2], af[mi][k][3],
                        smem_u32(&sA[arow][acol]));
        }
    }

    __half2 srh2[2][2];
    __half2 labR2[2][2];
#pragma unroll
    for (int mi = 0; mi < 2; mi++)
#pragma unroll
        for (int h = 0; h < 2; h++) {
            int r = wrow + 16 * mi + 8 * h + g;
            srh2[mi][h]  = __half2half2(sqAh[r]);
            labR2[mi][h] = __half2half2(labAh[r]);
        }

    const __half2 neg2 = __float2half2_rn(-2.f);
    float acc_all = 0.f, acc_same = 0.f;

#pragma unroll
    for (int ni2 = 0; ni2 < 4; ni2++) {
        uint32_t ac[2][2][2];
#pragma unroll
        for (int mi = 0; mi < 2; mi++)
#pragma unroll
            for (int ns = 0; ns < 2; ns++) { ac[mi][ns][0] = 0u; ac[mi][ns][1] = 0u; }

        const int brow = wcol + 16 * ni2 + lr + ((lq & 1) ? 8 : 0);
#pragma unroll
        for (int k = 0; k < 4; k++) {
            uint32_t b0, b1, b2, b3;
            ldmatrix_x4(b0, b1, b2, b3,
                        smem_u32(&sB[brow][k * 16 + ((lq & 2) ? 8 : 0)]));
#pragma unroll
            for (int mi = 0; mi < 2; mi++) {
                mma16816_f16(ac[mi][0], af[mi][k], b0, b2);
                mma16816_f16(ac[mi][1], af[mi][k], b1, b3);
            }
        }

        const bool useF = (ni2 == 1) && !diag;   // 25% on FMA pipe

        if (!diag) {
            __half2 allh  = __float2half2_rn(0.f);
            __half2 sameh = __float2half2_rn(0.f);
#pragma unroll
            for (int ns = 0; ns < 2; ns++) {
                const int c0 = wcol + 8 * (2 * ni2 + ns) + 2 * t4;
                const __half2 sc  = *(const __half2*)&sqBh[c0];
                const __half2 lc2 = *(const __half2*)&labBh[c0];
#pragma unroll
                for (int mi = 0; mi < 2; mi++)
#pragma unroll
                    for (int h = 0; h < 2; h++) {
                        __half2 g2  = *(const __half2*)&ac[mi][ns][h];
                        __half2 d2h = __hfma2(g2, neg2, __hadd2(srh2[mi][h], sc));
                        float d2a = __low2float(d2h);
                        float d2b = __high2float(d2h);
                        float da, db;
                        if (useF) { da = qroot_fma(d2a);  db = qroot_fma(d2b); }
                        else      { da = qroot_mufu(d2a); db = qroot_mufu(d2b); }
                        __half2 dist2 = __floats2half2_rn(da, db);
                        allh  = __hadd2(allh, dist2);
                        sameh = __hfma2(dist2, __heq2(labR2[mi][h], lc2), sameh);
                    }
            }
            float2 fa = __half22float2(allh);
            float2 fs = __half22float2(sameh);
            acc_all  += fa.x + fa.y;
            acc_same += fs.x + fs.y;
        } else {
            // diagonal tile: scalar masked path (3% of tiles)
#pragma unroll
            for (int ns = 0; ns < 2; ns++) {
                const int c0 = wcol + 8 * (2 * ni2 + ns) + 2 * t4;
                const __half2 sc  = *(const __half2*)&sqBh[c0];
                const __half2 lc2 = *(const __half2*)&labBh[c0];
#pragma unroll
                for (int mi = 0; mi < 2; mi++)
#pragma unroll
                    for (int h = 0; h < 2; h++) {
                        const int rv = wrow + 16 * mi + 8 * h + g;
                        __half2 g2  = *(const __half2*)&ac[mi][ns][h];
                        __half2 d2h = __hfma2(g2, neg2, __hadd2(srh2[mi][h], sc));
                        float d2a = fmaxf(__low2float(d2h), 0.f);
                        float d2b = fmaxf(__high2float(d2h), 0.f);
                        float da = qroot_mufu(d2a);
                        float db = qroot_mufu(d2b);
                        if (c0 > rv) {
                            acc_all += da;
                            if (__heq(__low2half(labR2[mi][h]), __low2half(lc2))) acc_same += da;
                        }
                        if (c0 + 1 > rv) {
                            acc_all += db;
                            if (__heq(__high2half(labR2[mi][h]), __high2half(lc2))) acc_same += db;
                        }
                    }
            }
        }
    }

    float accsum = fmaf(6.f, acc_same, -acc_all);   // 5*same - 1*diff

#pragma unroll
    for (int off = 16; off; off >>= 1)
        accsum += __shfl_xor_sync(0xFFFFFFFFu, accsum, off);
    if (lane == 0) wsum[w] = accsum;
    __syncthreads();
    if (tid == 0) {
        float s = 0.f;
#pragma unroll
        for (int i = 0; i < 8; i++) s += wsum[i];
        g_partial[blockIdx.x] = s;
    }
}

// ---------------------------------------------------------------------------
// Kernel 3: deterministic final reduction
// ---------------------------------------------------------------------------
__global__ void reduce_kernel(float* __restrict__ out) {
    __shared__ float sh[512];
    float s = 0.f;
    for (int i = threadIdx.x; i < NTILES; i += 512)
        s += g_partial[i];
    sh[threadIdx.x] = s;
    __syncthreads();
    for (int off = 256; off; off >>= 1) {
        if (threadIdx.x < off) sh[threadIdx.x] += sh[threadIdx.x + off];
        __syncthreads();
    }
    if (threadIdx.x == 0) out[0] = sh[0];
}

extern "C" void kernel_launch(void* const* d_in, const int* in_sizes, int n_in,
                              void* d_out, int out_size) {
    const float* outputs = (const float*)d_in[0];
    const int*   labels  = (const int*)d_in[1];
    float*       out     = (float*)d_out;

    prep_kernel<<<BQ / 16, 256>>>(outputs);
    pair_kernel<<<NTILES, 256>>>(labels);
    reduce_kernel<<<1, 512>>>(out);
}